// round 17
// baseline (speedup 1.0000x reference)
#include <cuda_runtime.h>

// WeightedLoss: mean over 64M elems of (target==1 ? 1-sigmoid(pred) : 0.1)
// 1 - sigmoid(x) = 0.5 - 0.5*tanh(x/2) -> single MUFU.TANH
//
// R17: WARP-level dynamic work stealing, zero barriers in the hot loop
// (R16's block-level version put 2 syncthreads per chunk -> regression).
// Each warp: atomicAdd grab -> 8 iters of 2x LDG.256 -> warp shfl reduce ->
// write partial to the chunk's FIXED slot (deterministic regardless of which
// warp ran it). Last block sums all slots in fixed order.

#define NBLOCKS (148 * 8)
#define NTHREADS 256
#define WARPS_PER_BLOCK (NTHREADS / 32)
#define CHUNK_ITERS 8
#define CHUNK_GROUPS (CHUNK_ITERS * 32)          // v8-groups per chunk = 256
#define NCHUNKS 32768                             // 8M groups / 256

__device__ float g_chunk_sum[NCHUNKS];
__device__ unsigned int g_work = 0;     // next chunk
__device__ unsigned int g_arrive = 0;   // blocks done

__device__ __forceinline__ float elem_loss(float p, int t) {
    float s = 0.5f - 0.5f * __tanhf(0.5f * p);   // = 1 - sigmoid(p)
    return (t == 1) ? s : 0.1f;
}

__device__ __forceinline__ void ldg256_f32(const float* a, float* v) {
    asm volatile("ld.global.v8.f32 {%0,%1,%2,%3,%4,%5,%6,%7}, [%8];"
                 : "=f"(v[0]), "=f"(v[1]), "=f"(v[2]), "=f"(v[3]),
                   "=f"(v[4]), "=f"(v[5]), "=f"(v[6]), "=f"(v[7])
                 : "l"(a));
}
__device__ __forceinline__ void ldg256_s32(const int* a, int* v) {
    asm volatile("ld.global.v8.u32 {%0,%1,%2,%3,%4,%5,%6,%7}, [%8];"
                 : "=r"(v[0]), "=r"(v[1]), "=r"(v[2]), "=r"(v[3]),
                   "=r"(v[4]), "=r"(v[5]), "=r"(v[6]), "=r"(v[7])
                 : "l"(a));
}

__global__ __launch_bounds__(NTHREADS)
void wl_warpdyn_kernel(const float* __restrict__ pred,
                       const int* __restrict__ tgt,
                       float inv_n,
                       float* __restrict__ out)
{
    const int lane = threadIdx.x & 31;

    // ---- barrier-free warp work-stealing loop ----
    for (;;) {
        unsigned int c;
        if (lane == 0) c = atomicAdd(&g_work, 1u);
        c = __shfl_sync(0xffffffffu, c, 0);
        if (c >= NCHUNKS) break;

        size_t base = (size_t)c * CHUNK_GROUPS + lane;
        float acc = 0.0f;
        #pragma unroll
        for (int it = 0; it < CHUNK_ITERS; it++) {
            size_t g = base + (size_t)it * 32;
            float p[8];
            int   t[8];
            ldg256_f32(pred + g * 8, p);
            ldg256_s32(tgt  + g * 8, t);
            #pragma unroll
            for (int k = 0; k < 8; k++)
                acc += elem_loss(p[k], t[k]);
        }
        // warp reduce (fixed order -> chunk partial is deterministic)
        #pragma unroll
        for (int o = 16; o > 0; o >>= 1)
            acc += __shfl_xor_sync(0xffffffffu, acc, o);
        if (lane == 0)
            g_chunk_sum[c] = acc;
    }

    // ---- single end-of-kernel sync + last-block final reduce ----
    __shared__ bool s_last;
    __syncthreads();
    if (threadIdx.x == 0) {
        __threadfence();
        unsigned int prev = atomicAdd(&g_arrive, 1u);
        s_last = (prev == (unsigned int)(gridDim.x - 1));
    }
    __syncthreads();

    if (s_last) {
        float a = 0.0f;
        for (int j = threadIdx.x; j < NCHUNKS; j += NTHREADS)
            a += g_chunk_sum[j];   // 128 per thread, fixed order, independent loads

        #pragma unroll
        for (int o = 16; o > 0; o >>= 1)
            a += __shfl_xor_sync(0xffffffffu, a, o);

        __shared__ float sw[WARPS_PER_BLOCK];
        if ((threadIdx.x & 31) == 0) sw[threadIdx.x >> 5] = a;
        __syncthreads();

        if (threadIdx.x < 32) {
            float v = (threadIdx.x < WARPS_PER_BLOCK) ? sw[threadIdx.x] : 0.0f;
            #pragma unroll
            for (int o = 4; o > 0; o >>= 1)
                v += __shfl_xor_sync(0xffffffffu, v, o);
            if (threadIdx.x == 0) {
                out[0] = v * inv_n;
                __threadfence();
                g_work = 0;        // re-arm for graph replay
                g_arrive = 0;
            }
        }
    }
}

extern "C" void kernel_launch(void* const* d_in, const int* in_sizes, int n_in,
                              void* d_out, int out_size)
{
    const float* pred = (const float*)d_in[0];
    const int*   tgt  = (const int*)d_in[1];
    float*       out  = (float*)d_out;
    const int n = in_sizes[0];   // 64M = NCHUNKS * CHUNK_GROUPS * 8 exactly

    wl_warpdyn_kernel<<<NBLOCKS, NTHREADS>>>(pred, tgt, 1.0f / (float)n, out);
}